// round 1
// baseline (speedup 1.0000x reference)
#include <cuda_runtime.h>
#include <mma.h>
#include <cstdint>

using namespace nvcuda;

#define DIM    512
#define NH     16
#define HD     32
#define NWIN   512      // 8 batches * 8*8 windows
#define NTOK   32768    // 512 windows * 64 tokens
#define NQKV   1536
#define WSCALE 0.17677669529663687f   // 32^-0.5

// GEMM tiling
#define BM 128
#define BN 64
#define BK 32
#define AST 36   // A smem row stride (floats)
#define BST 72   // B smem row stride
#define CST 68   // C smem row stride

// Scratch (allocation-free __device__ globals)
__device__ float g_q[(size_t)NWIN * NH * 64 * HD];
__device__ float g_k[(size_t)NWIN * NH * 64 * HD];
__device__ float g_v[(size_t)NWIN * NH * 64 * HD];
__device__ float g_ao[(size_t)NTOK * DIM];

__device__ __forceinline__ float tf32_rn(float x) {
    unsigned u;
    asm("cvt.rna.tf32.f32 %0, %1;" : "=r"(u) : "f"(x));
    return __uint_as_float(u);
}

__device__ __forceinline__ void split4(float4 v, float4& h, float4& l) {
    h.x = tf32_rn(v.x); l.x = tf32_rn(v.x - h.x);
    h.y = tf32_rn(v.y); l.y = tf32_rn(v.y - h.y);
    h.z = tf32_rn(v.z); l.z = tf32_rn(v.z - h.z);
    h.w = tf32_rn(v.w); l.w = tf32_rn(v.w - h.w);
}

// windowed row index -> global token index
__device__ __forceinline__ int win_token(int r) {
    int wid = r >> 6, n = r & 63;
    int b = wid >> 6, wy = (wid >> 3) & 7, wx = wid & 7;
    int h = wy * 8 + (n >> 3), w = wx * 8 + (n & 7);
    return (b << 12) + (h << 6) + w;
}

// C = A @ W + bias, compensated tf32 (hi*hi + hi*lo + lo*hi), fp32 accum.
// QKV_EPI: fused bias + axial RoPE + scatter to g_q/g_k/g_v.
// else:    fused bias + window->token remap into out.
template<int NCOLS, bool REMAP_IN, bool QKV_EPI>
__global__ void gemm_kernel(const float* __restrict__ A,
                            const float* __restrict__ W,
                            const float* __restrict__ bias,
                            float* __restrict__ out)
{
    extern __shared__ float sm[];
    float* a_hi = sm;                    // BM*AST
    float* a_lo = a_hi + BM * AST;
    float* b_hi = a_lo + BM * AST;       // BK*BST
    float* b_lo = b_hi + BK * BST;
    float* csm  = sm;                    // epilogue reuse (BM*CST <= 2*BM*AST)

    const float* Asrc = REMAP_IN ? A : g_ao;

    int tid  = threadIdx.x;
    int warp = tid >> 5;
    int wm = warp >> 1, wn = warp & 1;
    int rbase = blockIdx.x * BM;
    int nbase = blockIdx.y * BN;

    wmma::fragment<wmma::accumulator, 16, 16, 8, float> acc[2][2];
    #pragma unroll
    for (int i = 0; i < 2; i++)
        #pragma unroll
        for (int j = 0; j < 2; j++) wmma::fill_fragment(acc[i][j], 0.0f);

    for (int kt = 0; kt < DIM / BK; kt++) {
        __syncthreads();
        // Load A tile: 128 rows x 32 cols (8 float4/row)
        #pragma unroll
        for (int s4 = 0; s4 < 4; s4++) {
            int idx = tid + s4 * 256;
            int i = idx >> 3, c = idx & 7;
            int r = rbase + i;
            int t = REMAP_IN ? win_token(r) : r;
            float4 v = *reinterpret_cast<const float4*>(
                Asrc + (size_t)t * DIM + kt * BK + c * 4);
            float4 h, l; split4(v, h, l);
            *reinterpret_cast<float4*>(a_hi + i * AST + c * 4) = h;
            *reinterpret_cast<float4*>(a_lo + i * AST + c * 4) = l;
        }
        // Load B tile: 32 rows x 64 cols (16 float4/row)
        #pragma unroll
        for (int s4 = 0; s4 < 2; s4++) {
            int idx = tid + s4 * 256;
            int k = idx >> 4, c = idx & 15;
            float4 v = *reinterpret_cast<const float4*>(
                W + (size_t)(kt * BK + k) * NCOLS + nbase + c * 4);
            float4 h, l; split4(v, h, l);
            *reinterpret_cast<float4*>(b_hi + k * BST + c * 4) = h;
            *reinterpret_cast<float4*>(b_lo + k * BST + c * 4) = l;
        }
        __syncthreads();
        #pragma unroll
        for (int ks = 0; ks < 4; ks++) {
            wmma::fragment<wmma::matrix_a, 16, 16, 8, wmma::precision::tf32, wmma::row_major> fah[2], fal[2];
            wmma::fragment<wmma::matrix_b, 16, 16, 8, wmma::precision::tf32, wmma::row_major> fbh[2], fbl[2];
            #pragma unroll
            for (int i = 0; i < 2; i++) {
                int row = wm * 32 + i * 16;
                wmma::load_matrix_sync(fah[i], a_hi + row * AST + ks * 8, AST);
                wmma::load_matrix_sync(fal[i], a_lo + row * AST + ks * 8, AST);
            }
            #pragma unroll
            for (int j = 0; j < 2; j++) {
                int col = wn * 32 + j * 16;
                wmma::load_matrix_sync(fbh[j], b_hi + (ks * 8) * BST + col, BST);
                wmma::load_matrix_sync(fbl[j], b_lo + (ks * 8) * BST + col, BST);
            }
            #pragma unroll
            for (int i = 0; i < 2; i++)
                #pragma unroll
                for (int j = 0; j < 2; j++) {
                    wmma::mma_sync(acc[i][j], fah[i], fbh[j], acc[i][j]);
                    wmma::mma_sync(acc[i][j], fah[i], fbl[j], acc[i][j]);
                    wmma::mma_sync(acc[i][j], fal[i], fbh[j], acc[i][j]);
                }
        }
    }
    __syncthreads();
    #pragma unroll
    for (int i = 0; i < 2; i++)
        #pragma unroll
        for (int j = 0; j < 2; j++)
            wmma::store_matrix_sync(csm + (wm * 32 + i * 16) * CST + wn * 32 + j * 16,
                                    acc[i][j], CST, wmma::mem_row_major);
    __syncthreads();

    // Epilogue: 128x64 tile, 32 elems/thread
    for (int s4 = 0; s4 < (BM * BN) / 256; s4++) {
        int idx = tid + s4 * 256;
        int i = idx >> 6, cl = idx & 63;
        int r = rbase + i;
        int c = nbase + cl;
        float v = csm[i * CST + cl] + bias[c];
        if (QKV_EPI) {
            int wid = r >> 6, n = r & 63;
            int which = c >> 9;           // 0=q 1=k 2=v
            int cc = c & 511;
            int head = cc >> 5, d = cc & 31;
            float o;
            if (which < 2) {
                // axial 2D RoPE: dims 0..15 rotate with row pos, 16..31 with col pos
                int j16 = d & 15;
                int g   = d >> 4;
                int pos = g ? (n & 7) : (n >> 3);
                int jj  = j16 & 7;
                float invf = exp2f(-1.6609640474436813f * (float)jj); // 10000^(-jj/8)
                float ang = (float)pos * invf;
                float sn, cs;
                sincosf(ang, &sn, &cs);
                int off = (j16 < 8) ? 8 : -8;
                float vp = csm[i * CST + cl + off] + bias[c + off];
                o = (j16 < 8) ? (v * cs - vp * sn) : (v * cs + vp * sn);
            } else {
                o = v;
            }
            float* dst = (which == 0) ? g_q : (which == 1) ? g_k : g_v;
            dst[(((size_t)wid * NH + head) * 64 + n) * HD + d] = o;
        } else {
            int t = win_token(r);
            out[(size_t)t * DIM + c] = v;
        }
    }
}

// One CTA per (window, head): S = (Q*scale) K^T, softmax, O = A V.
// All GEMMs compensated tf32. Output stored un-windowed: g_ao[row][head*32+d].
__global__ void attn_kernel()
{
    extern __shared__ float sm[];
    float* qh = sm;                 // 64*36 each
    float* ql = qh + 64 * 36;
    float* kh = ql + 64 * 36;
    float* kl = kh + 64 * 36;
    float* vh = kl + 64 * 36;
    float* vl = vh + 64 * 36;
    float* s  = vl + 64 * 36;       // 64*68
    float* ah = sm;                 // reuse q/k region: 64*72
    float* al = ah + 64 * 72;       // ends exactly at vh

    int tid = threadIdx.x, warp = tid >> 5;
    int wid = blockIdx.x, head = blockIdx.y;
    size_t base = ((size_t)wid * NH + head) * (64 * HD);
    const float* qg = g_q + base;
    const float* kg = g_k + base;
    const float* vg = g_v + base;

    // Load Q (scaled), K, V -> hi/lo tf32 smem
    #pragma unroll
    for (int s4 = 0; s4 < 2; s4++) {
        int e = tid + s4 * 256;
        int n = e >> 3, d4 = e & 7;
        float4 v, h, l;
        v = *reinterpret_cast<const float4*>(qg + e * 4);
        v.x *= WSCALE; v.y *= WSCALE; v.z *= WSCALE; v.w *= WSCALE;
        split4(v, h, l);
        *reinterpret_cast<float4*>(qh + n * 36 + d4 * 4) = h;
        *reinterpret_cast<float4*>(ql + n * 36 + d4 * 4) = l;
        v = *reinterpret_cast<const float4*>(kg + e * 4);
        split4(v, h, l);
        *reinterpret_cast<float4*>(kh + n * 36 + d4 * 4) = h;
        *reinterpret_cast<float4*>(kl + n * 36 + d4 * 4) = l;
        v = *reinterpret_cast<const float4*>(vg + e * 4);
        split4(v, h, l);
        *reinterpret_cast<float4*>(vh + n * 36 + d4 * 4) = h;
        *reinterpret_cast<float4*>(vl + n * 36 + d4 * 4) = l;
    }
    __syncthreads();

    // S = Q K^T : 4x4 frags of 16x16, k=32
    for (int f = warp; f < 16; f += 8) {
        int mi = f >> 2, ni = f & 3;
        wmma::fragment<wmma::accumulator, 16, 16, 8, float> acc;
        wmma::fill_fragment(acc, 0.0f);
        #pragma unroll
        for (int ks = 0; ks < 4; ks++) {
            wmma::fragment<wmma::matrix_a, 16, 16, 8, wmma::precision::tf32, wmma::row_major> fah, fal;
            wmma::fragment<wmma::matrix_b, 16, 16, 8, wmma::precision::tf32, wmma::col_major> fbh, fbl;
            wmma::load_matrix_sync(fah, qh + (mi * 16) * 36 + ks * 8, 36);
            wmma::load_matrix_sync(fal, ql + (mi * 16) * 36 + ks * 8, 36);
            wmma::load_matrix_sync(fbh, kh + (ni * 16) * 36 + ks * 8, 36);
            wmma::load_matrix_sync(fbl, kl + (ni * 16) * 36 + ks * 8, 36);
            wmma::mma_sync(acc, fah, fbh, acc);
            wmma::mma_sync(acc, fah, fbl, acc);
            wmma::mma_sync(acc, fal, fbh, acc);
        }
        wmma::store_matrix_sync(s + (mi * 16) * 68 + ni * 16, acc, 68, wmma::mem_row_major);
    }
    __syncthreads();

    // Row softmax (64 rows), write A as hi/lo tf32
    if (tid < 64) {
        float* sr = s + tid * 68;
        float m = sr[0];
        #pragma unroll
        for (int c = 1; c < 64; c++) m = fmaxf(m, sr[c]);
        float sum = 0.f;
        #pragma unroll
        for (int c = 0; c < 64; c++) sum += expf(sr[c] - m);
        float inv = 1.f / sum;
        #pragma unroll
        for (int c = 0; c < 64; c++) {
            float a = expf(sr[c] - m) * inv;
            float hh = tf32_rn(a);
            ah[tid * 72 + c] = hh;
            al[tid * 72 + c] = tf32_rn(a - hh);
        }
    }
    __syncthreads();

    // O = A V : 4x2 frags of 16x16, k=64
    {
        int mi = warp >> 1, ni = warp & 1;
        wmma::fragment<wmma::accumulator, 16, 16, 8, float> acc;
        wmma::fill_fragment(acc, 0.0f);
        #pragma unroll
        for (int ks = 0; ks < 8; ks++) {
            wmma::fragment<wmma::matrix_a, 16, 16, 8, wmma::precision::tf32, wmma::row_major> fah, fal;
            wmma::fragment<wmma::matrix_b, 16, 16, 8, wmma::precision::tf32, wmma::row_major> fbh, fbl;
            wmma::load_matrix_sync(fah, ah + (mi * 16) * 72 + ks * 8, 72);
            wmma::load_matrix_sync(fal, al + (mi * 16) * 72 + ks * 8, 72);
            wmma::load_matrix_sync(fbh, vh + (ks * 8) * 36 + ni * 16, 36);
            wmma::load_matrix_sync(fbl, vl + (ks * 8) * 36 + ni * 16, 36);
            wmma::mma_sync(acc, fah, fbh, acc);
            wmma::mma_sync(acc, fah, fbl, acc);
            wmma::mma_sync(acc, fal, fbh, acc);
        }
        wmma::store_matrix_sync(
            g_ao + (size_t)(wid * 64 + mi * 16) * DIM + head * HD + ni * 16,
            acc, DIM, wmma::mem_row_major);
    }
}

extern "C" void kernel_launch(void* const* d_in, const int* in_sizes, int n_in,
                              void* d_out, int out_size)
{
    (void)in_sizes; (void)n_in; (void)out_size;
    const float* x      = (const float*)d_in[0];
    const float* qkv_w  = (const float*)d_in[1];
    const float* qkv_b  = (const float*)d_in[2];
    // d_in[3], d_in[4] (kv_w, kv_b) are dead code in the reference output
    const float* proj_w = (const float*)d_in[5];
    const float* proj_b = (const float*)d_in[6];
    float* out = (float*)d_out;

    const int gemm_smem = (2 * BM * AST + 2 * BK * BST) * 4;  // 55296 B
    const int attn_smem = (6 * 64 * 36 + 64 * 68) * 4;        // 72704 B

    cudaFuncSetAttribute(gemm_kernel<NQKV, true,  true>,
                         cudaFuncAttributeMaxDynamicSharedMemorySize, gemm_smem);
    cudaFuncSetAttribute(gemm_kernel<DIM,  false, false>,
                         cudaFuncAttributeMaxDynamicSharedMemorySize, gemm_smem);
    cudaFuncSetAttribute(attn_kernel,
                         cudaFuncAttributeMaxDynamicSharedMemorySize, attn_smem);

    gemm_kernel<NQKV, true, true>
        <<<dim3(NTOK / BM, NQKV / BN), 256, gemm_smem>>>(x, qkv_w, qkv_b, nullptr);
    attn_kernel<<<dim3(NWIN, NH), 256, attn_smem>>>();
    gemm_kernel<DIM, false, false>
        <<<dim3(NTOK / BM, DIM / BN), 256, gemm_smem>>>(nullptr, proj_w, proj_b, out);
}

// round 4
// speedup vs baseline: 2.6827x; 2.6827x over previous
#include <cuda_runtime.h>
#include <cuda_bf16.h>
#include <mma.h>
#include <cstdint>

using namespace nvcuda;
typedef __nv_bfloat16 bf16;

#define DIM    512
#define NH     16
#define HD     32
#define NWIN   512      // 8 batches * 8*8 windows
#define NTOK   32768    // 512 windows * 64 tokens
#define NQKV   1536
#define WSCALE 0.17677669529663687f   // 32^-0.5

// GEMM tiling
#define BM 128
#define BN 64
#define BK 32
#define SA 40   // A smem row stride (bf16 elems)
#define SB 72   // B smem row stride (bf16 elems)
#define SC 68   // C epilogue stride (f32)

// Scratch (allocation-free __device__ globals) — same 256MB plan as passing round 1
__device__ float g_q[(size_t)NWIN * NH * 64 * HD];
__device__ float g_k[(size_t)NWIN * NH * 64 * HD];
__device__ float g_v[(size_t)NWIN * NH * 64 * HD];
__device__ float g_ao[(size_t)NTOK * DIM];

__device__ __forceinline__ unsigned short us(bf16 v) { return __bfloat16_as_ushort(v); }

// split float4 -> packed bf16 hi pair-of-uint / lo pair-of-uint
__device__ __forceinline__ void split_pack(float4 v, uint2& ph, uint2& pl) {
    bf16 h0 = __float2bfloat16(v.x), h1 = __float2bfloat16(v.y);
    bf16 h2 = __float2bfloat16(v.z), h3 = __float2bfloat16(v.w);
    bf16 l0 = __float2bfloat16(v.x - __bfloat162float(h0));
    bf16 l1 = __float2bfloat16(v.y - __bfloat162float(h1));
    bf16 l2 = __float2bfloat16(v.z - __bfloat162float(h2));
    bf16 l3 = __float2bfloat16(v.w - __bfloat162float(h3));
    ph.x = us(h0) | ((unsigned)us(h1) << 16);
    ph.y = us(h2) | ((unsigned)us(h3) << 16);
    pl.x = us(l0) | ((unsigned)us(l1) << 16);
    pl.y = us(l2) | ((unsigned)us(l3) << 16);
}

// windowed row index -> global token index
__device__ __forceinline__ int win_token(int r) {
    int wid = r >> 6, n = r & 63;
    int b = wid >> 6, wy = (wid >> 3) & 7, wx = wid & 7;
    int h = wy * 8 + (n >> 3), w = wx * 8 + (n & 7);
    return (b << 12) + (h << 6) + w;
}

// C = A @ W + bias, compensated bf16 (hi*hi + hi*lo + lo*hi), fp32 accum.
// In-kernel split from f32 sources (round-1 structure, bf16 MMA).
template<int NCOLS, bool REMAP_IN, bool QKV_EPI>
__global__ void gemm_kernel(const float* __restrict__ A,
                            const float* __restrict__ W,
                            const float* __restrict__ bias,
                            float* __restrict__ out)
{
    extern __shared__ __align__(16) char smraw[];
    bf16* smb = reinterpret_cast<bf16*>(smraw);
    // bf16-elem offsets: a_hi 0, a_lo 5120, b_hi 10240, b_lo 12544 (end 14848)

    const float* Asrc = REMAP_IN ? A : g_ao;

    int tid  = threadIdx.x;
    int warp = tid >> 5;
    int wm = warp >> 1, wn = warp & 1;
    int rbase = blockIdx.x * BM;
    int nbase = blockIdx.y * BN;

    wmma::fragment<wmma::accumulator, 16, 16, 16, float> acc[2][2];
    #pragma unroll
    for (int i = 0; i < 2; i++)
        #pragma unroll
        for (int j = 0; j < 2; j++) wmma::fill_fragment(acc[i][j], 0.0f);

    for (int kt = 0; kt < DIM / BK; kt++) {
        __syncthreads();
        // A tile: 128 rows x 32 cols (8 float4 per row)
        #pragma unroll
        for (int s4 = 0; s4 < 4; s4++) {
            int idx = tid + s4 * 256;
            int i = idx >> 3, c = idx & 7;
            int r = rbase + i;
            int t = REMAP_IN ? win_token(r) : r;
            float4 v = *reinterpret_cast<const float4*>(
                Asrc + (size_t)t * DIM + kt * BK + c * 4);
            uint2 ph, pl; split_pack(v, ph, pl);
            *reinterpret_cast<uint2*>(smb + i * SA + c * 4)        = ph;
            *reinterpret_cast<uint2*>(smb + 5120 + i * SA + c * 4) = pl;
        }
        // B tile: 32 rows x 64 cols (16 float4 per row)
        #pragma unroll
        for (int s4 = 0; s4 < 2; s4++) {
            int idx = tid + s4 * 256;
            int k = idx >> 4, c = idx & 15;
            float4 v = *reinterpret_cast<const float4*>(
                W + (size_t)(kt * BK + k) * NCOLS + nbase + c * 4);
            uint2 ph, pl; split_pack(v, ph, pl);
            *reinterpret_cast<uint2*>(smb + 10240 + k * SB + c * 4) = ph;
            *reinterpret_cast<uint2*>(smb + 12544 + k * SB + c * 4) = pl;
        }
        __syncthreads();
        #pragma unroll
        for (int ks = 0; ks < 2; ks++) {
            wmma::fragment<wmma::matrix_a, 16, 16, 16, bf16, wmma::row_major> fah[2], fal[2];
            wmma::fragment<wmma::matrix_b, 16, 16, 16, bf16, wmma::row_major> fbh[2], fbl[2];
            #pragma unroll
            for (int i = 0; i < 2; i++) {
                int row = wm * 32 + i * 16;
                wmma::load_matrix_sync(fah[i], smb + row * SA + ks * 16, SA);
                wmma::load_matrix_sync(fal[i], smb + 5120 + row * SA + ks * 16, SA);
            }
            #pragma unroll
            for (int j = 0; j < 2; j++) {
                int col = wn * 32 + j * 16;
                wmma::load_matrix_sync(fbh[j], smb + 10240 + (ks * 16) * SB + col, SB);
                wmma::load_matrix_sync(fbl[j], smb + 12544 + (ks * 16) * SB + col, SB);
            }
            #pragma unroll
            for (int i = 0; i < 2; i++)
                #pragma unroll
                for (int j = 0; j < 2; j++) {
                    wmma::mma_sync(acc[i][j], fah[i], fbh[j], acc[i][j]);
                    wmma::mma_sync(acc[i][j], fah[i], fbl[j], acc[i][j]);
                    wmma::mma_sync(acc[i][j], fal[i], fbh[j], acc[i][j]);
                }
        }
    }
    __syncthreads();
    float* csm = reinterpret_cast<float*>(smraw);
    #pragma unroll
    for (int i = 0; i < 2; i++)
        #pragma unroll
        for (int j = 0; j < 2; j++)
            wmma::store_matrix_sync(csm + (wm * 32 + i * 16) * SC + wn * 32 + j * 16,
                                    acc[i][j], SC, wmma::mem_row_major);
    __syncthreads();

    // Epilogue: 128x64 tile, 32 elems/thread (identical to round 1)
    for (int s4 = 0; s4 < (BM * BN) / 256; s4++) {
        int idx = tid + s4 * 256;
        int i = idx >> 6, cl = idx & 63;
        int r = rbase + i;
        int c = nbase + cl;
        float v = csm[i * SC + cl] + bias[c];
        if (QKV_EPI) {
            int wid = r >> 6, n = r & 63;
            int which = c >> 9;           // 0=q 1=k 2=v
            int cc = c & 511;
            int head = cc >> 5, d = cc & 31;
            float o;
            if (which < 2) {
                // axial 2D RoPE: dims 0..15 rotate with row pos, 16..31 with col pos
                int j16 = d & 15;
                int g   = d >> 4;
                int pos = g ? (n & 7) : (n >> 3);
                int jj  = j16 & 7;
                float invf = exp2f(-1.6609640474436813f * (float)jj); // 10000^(-jj/8)
                float ang = (float)pos * invf;
                float sn, cs;
                sincosf(ang, &sn, &cs);
                int off = (j16 < 8) ? 8 : -8;
                float vp = csm[i * SC + cl + off] + bias[c + off];
                o = (j16 < 8) ? (v * cs - vp * sn) : (v * cs + vp * sn);
            } else {
                o = v;
            }
            float* dst = (which == 0) ? g_q : (which == 1) ? g_k : g_v;
            dst[(((size_t)wid * NH + head) * 64 + n) * HD + d] = o;
        } else {
            int t = win_token(r);
            out[(size_t)t * DIM + c] = v;
        }
    }
}

// One CTA per (window, head): S = (Q*scale) K^T, softmax, O = A V.
// Compensated bf16 MMA; f32 in/out globals (round-1 structure).
__global__ void attn_kernel()
{
    extern __shared__ __align__(16) char smraw[];
    bf16* smb = reinterpret_cast<bf16*>(smraw);
    // bf16-elem offsets: qh 0, ql 2560, kh 5120, kl 7680, vh 10240, vl 12800 (end 15360)
    float* s = reinterpret_cast<float*>(smraw + 30720);   // 64x68 f32
    bf16* ah = smb;                                        // overlay 64x72 over q/k (dead after S)
    bf16* al = smb + 4608;                                 // ends 9216 < 10240 (vh safe)

    int tid = threadIdx.x, warp = tid >> 5;
    int wid = blockIdx.x, head = blockIdx.y;
    size_t base = ((size_t)wid * NH + head) * (64 * HD);
    const float* qg = g_q + base;
    const float* kg = g_k + base;
    const float* vg = g_v + base;

    // Load Q (scaled), K, V -> hi/lo bf16 smem
    #pragma unroll
    for (int s4 = 0; s4 < 2; s4++) {
        int e = tid + s4 * 256;
        int n = e >> 3, d4 = e & 7;
        float4 v; uint2 ph, pl;
        v = *reinterpret_cast<const float4*>(qg + e * 4);
        v.x *= WSCALE; v.y *= WSCALE; v.z *= WSCALE; v.w *= WSCALE;
        split_pack(v, ph, pl);
        *reinterpret_cast<uint2*>(smb + n * SA + d4 * 4)        = ph;
        *reinterpret_cast<uint2*>(smb + 2560 + n * SA + d4 * 4) = pl;
        v = *reinterpret_cast<const float4*>(kg + e * 4);
        split_pack(v, ph, pl);
        *reinterpret_cast<uint2*>(smb + 5120 + n * SA + d4 * 4) = ph;
        *reinterpret_cast<uint2*>(smb + 7680 + n * SA + d4 * 4) = pl;
        v = *reinterpret_cast<const float4*>(vg + e * 4);
        split_pack(v, ph, pl);
        *reinterpret_cast<uint2*>(smb + 10240 + n * SA + d4 * 4) = ph;
        *reinterpret_cast<uint2*>(smb + 12800 + n * SA + d4 * 4) = pl;
    }
    __syncthreads();

    // S = Q K^T : 16 frags of 16x16, 2 per warp
    #pragma unroll
    for (int fi = 0; fi < 2; fi++) {
        int f = warp + fi * 8;
        int mi = f >> 2, ni = f & 3;
        wmma::fragment<wmma::accumulator, 16, 16, 16, float> acc;
        wmma::fill_fragment(acc, 0.0f);
        #pragma unroll
        for (int ks = 0; ks < 2; ks++) {
            wmma::fragment<wmma::matrix_a, 16, 16, 16, bf16, wmma::row_major> fah, fal;
            wmma::fragment<wmma::matrix_b, 16, 16, 16, bf16, wmma::col_major> fbh, fbl;
            wmma::load_matrix_sync(fah, smb + (mi * 16) * SA + ks * 16, SA);
            wmma::load_matrix_sync(fal, smb + 2560 + (mi * 16) * SA + ks * 16, SA);
            wmma::load_matrix_sync(fbh, smb + 5120 + (ni * 16) * SA + ks * 16, SA);
            wmma::load_matrix_sync(fbl, smb + 7680 + (ni * 16) * SA + ks * 16, SA);
            wmma::mma_sync(acc, fah, fbh, acc);
            wmma::mma_sync(acc, fah, fbl, acc);
            wmma::mma_sync(acc, fal, fbh, acc);
        }
        wmma::store_matrix_sync(s + (mi * 16) * SC + ni * 16, acc, SC, wmma::mem_row_major);
    }
    __syncthreads();

    // Row softmax (64 rows), write A hi/lo bf16
    if (tid < 64) {
        float* sr = s + tid * SC;
        float m = sr[0];
        #pragma unroll
        for (int c = 1; c < 64; c++) m = fmaxf(m, sr[c]);
        float sum = 0.f;
        #pragma unroll
        for (int c = 0; c < 64; c++) { float e = expf(sr[c] - m); sr[c] = e; sum += e; }
        float inv = 1.f / sum;
        #pragma unroll
        for (int c = 0; c < 64; c++) {
            float a = sr[c] * inv;
            bf16 h = __float2bfloat16(a);
            ah[tid * SB + c] = h;
            al[tid * SB + c] = __float2bfloat16(a - __bfloat162float(h));
        }
    }
    __syncthreads();

    // O = A V : 8 frags (4x2), one per warp; store f32 direct to g_ao (round-1 style)
    {
        int mi = warp >> 1, ni = warp & 1;
        wmma::fragment<wmma::accumulator, 16, 16, 16, float> acc;
        wmma::fill_fragment(acc, 0.0f);
        #pragma unroll
        for (int ks = 0; ks < 4; ks++) {
            wmma::fragment<wmma::matrix_a, 16, 16, 16, bf16, wmma::row_major> fah, fal;
            wmma::fragment<wmma::matrix_b, 16, 16, 16, bf16, wmma::row_major> fbh, fbl;
            wmma::load_matrix_sync(fah, ah + (mi * 16) * SB + ks * 16, SB);
            wmma::load_matrix_sync(fal, al + (mi * 16) * SB + ks * 16, SB);
            wmma::load_matrix_sync(fbh, smb + 10240 + (ks * 16) * SA + ni * 16, SA);
            wmma::load_matrix_sync(fbl, smb + 12800 + (ks * 16) * SA + ni * 16, SA);
            wmma::mma_sync(acc, fah, fbh, acc);
            wmma::mma_sync(acc, fah, fbl, acc);
            wmma::mma_sync(acc, fal, fbh, acc);
        }
        wmma::store_matrix_sync(
            g_ao + (size_t)(wid * 64 + mi * 16) * DIM + head * HD + ni * 16,
            acc, DIM, wmma::mem_row_major);
    }
}

extern "C" void kernel_launch(void* const* d_in, const int* in_sizes, int n_in,
                              void* d_out, int out_size)
{
    (void)in_sizes; (void)n_in; (void)out_size;
    const float* x      = (const float*)d_in[0];
    const float* qkv_w  = (const float*)d_in[1];
    const float* qkv_b  = (const float*)d_in[2];
    // d_in[3], d_in[4] (kv_w, kv_b) are dead code in the reference output
    const float* proj_w = (const float*)d_in[5];
    const float* proj_b = (const float*)d_in[6];
    float* out = (float*)d_out;

    const int gemm_smem = BM * SC * 4;            // 34816 B (tiles need 29696)
    const int attn_smem = 30720 + 64 * SC * 4;    // 48128 B  (< 48KB default limit)

    gemm_kernel<NQKV, true, true>
        <<<dim3(NTOK / BM, NQKV / BN), 256, gemm_smem>>>(x, qkv_w, qkv_b, nullptr);
    attn_kernel<<<dim3(NWIN, NH), 256, attn_smem>>>();
    gemm_kernel<DIM, false, false>
        <<<dim3(NTOK / BM, DIM / BN), 256, gemm_smem>>>(nullptr, proj_w, proj_b, out);
}